// round 1
// baseline (speedup 1.0000x reference)
#include <cuda_runtime.h>
#include <math.h>

#define BATCH   32
#define DIM     2048
#define NH      32
#define NKV     8
#define HD      64
#define REP     4
#define MAXS    2048
#define SP      2047
#define NSPLIT  8
#define CHUNK   256     // L positions per attention block
#define TILE    64      // smem tile of L positions
#define KSPLIT  8
#define KCHUNK  (DIM / KSPLIT)   // 256

// ---------------- scratch (device globals; no allocation) ----------------
__device__ __align__(16) float g_qkv_part[KSPLIT * BATCH * 3072];
__device__ __align__(16) float g_q      [BATCH * DIM];          // roped Q, [b][head*64+d]
__device__ __align__(16) float g_knew   [BATCH * NKV * HD];     // roped new K (pos 2047)
__device__ __align__(16) float g_vnew   [BATCH * NKV * HD];     // new V (pos 2047)
__device__ __align__(16) float g_part_o [BATCH * NKV * NSPLIT * REP * HD];
__device__ __align__(16) float g_part_ms[BATCH * NKV * NSPLIT * REP * 2];
__device__ __align__(16) float g_attn   [BATCH * DIM];          // attention output
__device__ __align__(16) float g_o_part [KSPLIT * BATCH * DIM];

// ---------------- skinny GEMM: [32 x 2048] @ [2048 x OUTC], split-K ----------------
// grid: (OUTC/64, KSPLIT), block: 256.  Partials written to scratch (no atomics).
template<int OUTC>
__global__ __launch_bounds__(256) void gemm32_kernel(
    const float* __restrict__ Xin,
    const float* __restrict__ W0,
    const float* __restrict__ W1,
    const float* __restrict__ W2)
{
    __shared__ __align__(16) float Xs[32][36];   // pad: scalar access, conflict-free
    __shared__ __align__(16) float Ws[32][64];   // rows 256B, float4-friendly

    const float* X    = (OUTC == 3072) ? Xin : g_attn;
    float*       outp = (OUTC == 3072) ? g_qkv_part : g_o_part;

    int jbase = blockIdx.x * 64;
    const float* W = W0; int wcols = DIM; int jloc = jbase;
    if (OUTC == 3072) {
        if (jbase >= 2560)      { W = W2; wcols = 512; jloc = jbase - 2560; }
        else if (jbase >= 2048) { W = W1; wcols = 512; jloc = jbase - 2048; }
    }

    int t  = threadIdx.x;
    int n4 = (t & 15) << 2;        // 4 output columns
    int mb = (t >> 4) << 1;        // 2 output rows
    float4 a0 = make_float4(0.f, 0.f, 0.f, 0.f);
    float4 a1 = make_float4(0.f, 0.f, 0.f, 0.f);

    int kbeg = blockIdx.y * KCHUNK;
    for (int k0 = kbeg; k0 < kbeg + KCHUNK; k0 += 32) {
        {   // X tile: 32x32
            int m = t >> 3, c = (t & 7) << 2;
            float4 xv = *(const float4*)&X[m * DIM + k0 + c];
            Xs[m][c] = xv.x; Xs[m][c+1] = xv.y; Xs[m][c+2] = xv.z; Xs[m][c+3] = xv.w;
        }
        #pragma unroll
        for (int i = 0; i < 2; ++i) {   // W tile: 32x64
            int q = t + (i << 8);
            int kk = q >> 4, c = (q & 15) << 2;
            *(float4*)&Ws[kk][c] = *(const float4*)&W[(k0 + kk) * wcols + jloc + c];
        }
        __syncthreads();
        #pragma unroll
        for (int kk = 0; kk < 32; ++kk) {
            float4 w4 = *(const float4*)&Ws[kk][n4];
            float x0 = Xs[mb][kk], x1 = Xs[mb + 1][kk];
            a0.x += x0 * w4.x; a0.y += x0 * w4.y; a0.z += x0 * w4.z; a0.w += x0 * w4.w;
            a1.x += x1 * w4.x; a1.y += x1 * w4.y; a1.z += x1 * w4.z; a1.w += x1 * w4.w;
        }
        __syncthreads();
    }
    int ks = blockIdx.y;
    *(float4*)&outp[(ks * 32 + mb    ) * OUTC + jbase + n4] = a0;
    *(float4*)&outp[(ks * 32 + mb + 1) * OUTC + jbase + n4] = a1;
}

// ---------------- reduce K-split partials + RoPE ----------------
// grid: 192 x 256.  Each thread owns one even/odd pair (rotary pair).
__global__ __launch_bounds__(256) void rope_finalize_kernel()
{
    int pid = blockIdx.x * 256 + threadIdx.x;          // 0 .. 49151
    int b = pid / 1536;
    int j = (pid - b * 1536) * 2;                      // 0 .. 3070, even
    float v0 = 0.f, v1 = 0.f;
    #pragma unroll
    for (int s = 0; s < KSPLIT; ++s) {
        float2 p = *(const float2*)&g_qkv_part[(s * BATCH + b) * 3072 + j];
        v0 += p.x; v1 += p.y;
    }
    if (j < 2560) {
        int i2 = j & 63;   // 2*i within the head
        // inv = 10000^(-2i/64) in f32, matching reference precision class
        float inv = exp2f(-(float)i2 * (13.287712379549449f / 64.f));
        float ang = 2047.0f * inv;
        float sn, cs;
        sincosf(ang, &sn, &cs);
        float r0 = v0 * cs - v1 * sn;
        float r1 = v0 * sn + v1 * cs;
        if (j < 2048) {
            g_q[b * DIM + j]     = r0;
            g_q[b * DIM + j + 1] = r1;
        } else {
            g_knew[b * 512 + j - 2048] = r0;
            g_knew[b * 512 + j - 2047] = r1;
        }
    } else {
        g_vnew[b * 512 + j - 2560] = v0;
        g_vnew[b * 512 + j - 2559] = v1;
    }
}

// ---------------- flash-decode attention, split over L ----------------
// grid: (NSPLIT, NKV, BATCH), block 256.  Thread map: (h = t/64, x = t%64).
__global__ __launch_bounds__(256) void attn_kernel(
    const float* __restrict__ cache_k, const float* __restrict__ cache_v)
{
    __shared__ __align__(16) float Ksh[TILE][HD + 4];   // row = 272B (16B multiple)
    __shared__ __align__(16) float Vsh[TILE][HD + 4];
    __shared__ __align__(16) float qs [REP][HD];
    __shared__ __align__(16) float psh[REP][TILE];
    __shared__ float wred[8];
    __shared__ float m_s[REP], s_s[REP], mnew_s[REP], alpha_s[REP];

    int split = blockIdx.x, kv = blockIdx.y, b = blockIdx.z;
    int t = threadIdx.x;
    int h = t >> 6, xi = t & 63;           // xi: l in score phase, d in o phase
    int lane = t & 31, warp = t >> 5;      // each warp: fixed h, 32 l values

    qs[h][xi] = g_q[b * DIM + (kv * REP + h) * HD + xi] * 0.125f;  // pre-scale
    if (t < REP) { m_s[t] = -1e30f; s_s[t] = 0.f; }
    float o_acc = 0.f;
    __syncthreads();

    for (int tt = 0; tt < CHUNK / TILE; ++tt) {
        int l0 = split * CHUNK + tt * TILE;
        // load K/V tile: 64 rows x 256B, half-warp-contiguous float4
        #pragma unroll
        for (int i = 0; i < 4; ++i) {
            int q4 = t + (i << 8);
            int l = q4 >> 4, c = (q4 & 15) << 2;
            int lg = l0 + l;
            float4 k4, v4;
            if (lg == SP) {   // new token, not in the (unmodified) input cache
                k4 = *(const float4*)&g_knew[(b * NKV + kv) * HD + c];
                v4 = *(const float4*)&g_vnew[(b * NKV + kv) * HD + c];
            } else {
                int base = ((b * MAXS + lg) * NKV + kv) * HD + c;
                k4 = *(const float4*)&cache_k[base];
                v4 = *(const float4*)&cache_v[base];
            }
            *(float4*)&Ksh[l][c] = k4;
            *(float4*)&Vsh[l][c] = v4;
        }
        __syncthreads();

        // scores: thread (h, l=xi), float4 smem reads (conflict-free with pad 68)
        float sc = 0.f;
        const float4* qv  = (const float4*)&qs[h][0];
        const float4* kvp = (const float4*)&Ksh[xi][0];
        #pragma unroll
        for (int d4 = 0; d4 < HD / 4; ++d4) {
            float4 a = qv[d4], c4 = kvp[d4];
            sc += a.x * c4.x; sc += a.y * c4.y; sc += a.z * c4.z; sc += a.w * c4.w;
        }
        float wm = sc;
        #pragma unroll
        for (int o = 16; o; o >>= 1) wm = fmaxf(wm, __shfl_xor_sync(0xffffffffu, wm, o));
        if (lane == 0) wred[warp] = wm;
        __syncthreads();
        if (t < REP) {
            float tm = fmaxf(wred[2 * t], wred[2 * t + 1]);
            float mo = m_s[t];
            float mn = fmaxf(mo, tm);
            mnew_s[t]  = mn;
            alpha_s[t] = __expf(mo - mn);
            m_s[t]     = mn;
        }
        __syncthreads();
        float p = __expf(sc - mnew_s[h]);
        psh[h][xi] = p;
        float wsum = p;
        #pragma unroll
        for (int o = 16; o; o >>= 1) wsum += __shfl_xor_sync(0xffffffffu, wsum, o);
        if (lane == 0) wred[warp] = wsum;
        o_acc *= alpha_s[h];
        __syncthreads();
        if (t < REP) s_s[t] = s_s[t] * alpha_s[t] + wred[2 * t] + wred[2 * t + 1];
        // o accumulation: thread (h, d=xi); psh broadcast, Vsh row conflict-free
        #pragma unroll
        for (int l4 = 0; l4 < TILE / 4; ++l4) {
            float4 p4 = *(const float4*)&psh[h][l4 << 2];
            int lb = l4 << 2;
            o_acc += p4.x * Vsh[lb    ][xi];
            o_acc += p4.y * Vsh[lb + 1][xi];
            o_acc += p4.z * Vsh[lb + 2][xi];
            o_acc += p4.w * Vsh[lb + 3][xi];
        }
        __syncthreads();
    }

    g_part_o[(((b * NKV + kv) * NSPLIT + split) * REP + h) * HD + xi] = o_acc;
    if (t < 2 * REP) {
        int hh = t >> 1;
        g_part_ms[(((b * NKV + kv) * NSPLIT + split) * REP + hh) * 2 + (t & 1)]
            = (t & 1) ? s_s[hh] : m_s[hh];
    }
}

// ---------------- combine splits (log-sum-exp merge) ----------------
// grid: 1024 (b*head), block: 64 (d)
__global__ __launch_bounds__(64) void combine_kernel()
{
    int bh = blockIdx.x;
    int b = bh >> 5, head = bh & 31;
    int kv = head >> 2, h = head & 3;
    int d = threadIdx.x;

    float ms[NSPLIT], ss[NSPLIT];
    float gm = -1e30f;
    #pragma unroll
    for (int s = 0; s < NSPLIT; ++s) {
        int mi = (((b * NKV + kv) * NSPLIT + s) * REP + h) * 2;
        ms[s] = g_part_ms[mi];
        ss[s] = g_part_ms[mi + 1];
        gm = fmaxf(gm, ms[s]);
    }
    float S = 0.f, o = 0.f;
    #pragma unroll
    for (int s = 0; s < NSPLIT; ++s) {
        float w = __expf(ms[s] - gm);
        S += ss[s] * w;
        o += g_part_o[(((b * NKV + kv) * NSPLIT + s) * REP + h) * HD + d] * w;
    }
    g_attn[b * DIM + head * HD + d] = o / S;
}

// ---------------- final O-proj partial reduce ----------------
__global__ __launch_bounds__(256) void oreduce_kernel(float* __restrict__ out)
{
    int i = blockIdx.x * 256 + threadIdx.x;   // 0 .. 65535
    float v = 0.f;
    #pragma unroll
    for (int s = 0; s < KSPLIT; ++s) v += g_o_part[s * BATCH * DIM + i];
    out[i] = v;
}

// ---------------- launch ----------------
extern "C" void kernel_launch(void* const* d_in, const int* in_sizes, int n_in,
                              void* d_out, int out_size)
{
    const float* x  = (const float*)d_in[0];
    const float* qw = (const float*)d_in[1];
    const float* kw = (const float*)d_in[2];
    const float* vw = (const float*)d_in[3];
    const float* ow = (const float*)d_in[4];
    const float* ck = (const float*)d_in[5];
    const float* cv = (const float*)d_in[6];
    float* out = (float*)d_out;

    gemm32_kernel<3072><<<dim3(48, KSPLIT), 256>>>(x, qw, kw, vw);
    rope_finalize_kernel<<<192, 256>>>();
    attn_kernel<<<dim3(NSPLIT, NKV, BATCH), 256>>>(ck, cv);
    combine_kernel<<<1024, 64>>>();
    gemm32_kernel<2048><<<dim3(32, KSPLIT), 256>>>(nullptr, ow, nullptr, nullptr);
    oreduce_kernel<<<256, 256>>>(out);
}